// round 8
// baseline (speedup 1.0000x reference)
#include <cuda_runtime.h>
#include <cuda_bf16.h>
#include <math.h>
#include <stdint.h>

#define BATCH 2
#define SEQ   2048
#define DIM   4096
#define NH    32
#define NKV   8
#define HD    128
#define MROWS 4096
#define KVDIM 1024
#define KDIM  4096          // inner K of every projection

// ---------------- scratch (zero-init .bss) ----------------------------------
__device__ float g_q   [(size_t)MROWS * DIM];
__device__ float g_k   [(size_t)MROWS * KVDIM];
__device__ float g_v   [(size_t)MROWS * KVDIM];
__device__ float g_attn[(size_t)MROWS * DIM];

// int8 two-digit operands: chain1 = a1 (K bytes/row), chain2 = interleaved (2K bytes/row)
__device__ int8_t g_x1 [(size_t)MROWS * KDIM];
__device__ int8_t g_x2 [(size_t)MROWS * 2 * KDIM];
__device__ int8_t g_at1[(size_t)MROWS * KDIM];
__device__ int8_t g_at2[(size_t)MROWS * 2 * KDIM];
__device__ int8_t g_wq1[(size_t)DIM   * KDIM];
__device__ int8_t g_wq2[(size_t)DIM   * 2 * KDIM];
__device__ int8_t g_wk1[(size_t)KVDIM * KDIM];
__device__ int8_t g_wk2[(size_t)KVDIM * 2 * KDIM];
__device__ int8_t g_wv1[(size_t)KVDIM * KDIM];
__device__ int8_t g_wv2[(size_t)KVDIM * 2 * KDIM];
__device__ int8_t g_wo1[(size_t)DIM   * KDIM];
__device__ int8_t g_wo2[(size_t)DIM   * 2 * KDIM];

__device__ float g_sx [MROWS];
__device__ float g_sat[MROWS];
__device__ float g_swq[DIM];
__device__ float g_swk[KVDIM];
__device__ float g_swv[KVDIM];
__device__ float g_swo[DIM];

// attention split operands (bf16 3-term, as in R5)
__device__ uint16_t g_qs2[(size_t)BATCH * NH  * SEQ * 384];
__device__ uint16_t g_ks2[(size_t)BATCH * NKV * SEQ * 384];
__device__ uint16_t g_vs2[(size_t)BATCH * NKV * (3*SEQ) * HD];

// ---------------- helpers ----------------------------------------------------
__device__ __forceinline__ uint32_t smem_u32(const void* p) {
    return (uint32_t)__cvta_generic_to_shared(p);
}
__device__ __forceinline__ void cp_async16(uint32_t dst, const void* src) {
    asm volatile("cp.async.cg.shared.global [%0], [%1], 16;" :: "r"(dst), "l"(src) : "memory");
}
__device__ __forceinline__ void cp_commit() {
    asm volatile("cp.async.commit_group;" ::: "memory");
}

#define LDSM_X4(r0, r1, r2, r3, addr) \
    asm volatile("ldmatrix.sync.aligned.m8n8.x4.shared.b16 {%0,%1,%2,%3}, [%4];" \
                 : "=r"(r0), "=r"(r1), "=r"(r2), "=r"(r3) : "r"(addr))

#define LDSM_X4_T(r0, r1, r2, r3, addr) \
    asm volatile("ldmatrix.sync.aligned.m8n8.x4.trans.shared.b16 {%0,%1,%2,%3}, [%4];" \
                 : "=r"(r0), "=r"(r1), "=r"(r2), "=r"(r3) : "r"(addr))

#define MMA_BF16(d, a, b0v, b1v) \
    asm volatile("mma.sync.aligned.m16n8k16.row.col.f32.bf16.bf16.f32 " \
                 "{%0,%1,%2,%3}, {%4,%5,%6,%7}, {%8,%9}, {%0,%1,%2,%3};" \
                 : "+f"((d)[0]), "+f"((d)[1]), "+f"((d)[2]), "+f"((d)[3]) \
                 : "r"((a)[0]), "r"((a)[1]), "r"((a)[2]), "r"((a)[3]), \
                   "r"(b0v), "r"(b1v))

#define MMA_S8(d, a, b0v, b1v) \
    asm volatile("mma.sync.aligned.m16n8k32.row.col.s32.s8.s8.s32 " \
                 "{%0,%1,%2,%3}, {%4,%5,%6,%7}, {%8,%9}, {%0,%1,%2,%3};" \
                 : "+r"((d)[0]), "+r"((d)[1]), "+r"((d)[2]), "+r"((d)[3]) \
                 : "r"((a)[0]), "r"((a)[1]), "r"((a)[2]), "r"((a)[3]), \
                   "r"(b0v), "r"(b1v))

__device__ __forceinline__ void split2(float f, uint16_t& hb, uint16_t& lb) {
    __nv_bfloat16 hi = __float2bfloat16_rn(f);
    __nv_bfloat16 lo = __float2bfloat16_rn(f - __bfloat162float(hi));
    hb = __bfloat16_as_ushort(hi);
    lb = __bfloat16_as_ushort(lo);
}

// ---------------------------------------------------------------------------
// Row quantization: one block per row of 4096 fp32.
// value = s * (128*a1 + a0). chain1: a1. chain2: AMODE=1 (A-side): (a1,a0);
// AMODE=0 (B-side): (a0,a1)  [so A-chain2 dot B-chain2 = a1*b0 + a0*b1]
// ---------------------------------------------------------------------------
template <int AMODE>
__global__ void __launch_bounds__(256) quant_row(
    const float* __restrict__ src, int8_t* __restrict__ c1,
    int8_t* __restrict__ c2, float* __restrict__ sc)
{
    __shared__ float warpmax[8];
    const int row = blockIdx.x;
    const int tid = threadIdx.x;
    const int wid = tid >> 5, lane = tid & 31;

    const float4* p4 = (const float4*)(src + (size_t)row * KDIM) + tid * 4;
    float4 v0 = p4[0], v1 = p4[1], v2 = p4[2], v3 = p4[3];
    float f[16] = {v0.x,v0.y,v0.z,v0.w, v1.x,v1.y,v1.z,v1.w,
                   v2.x,v2.y,v2.z,v2.w, v3.x,v3.y,v3.z,v3.w};

    float am = 0.0f;
#pragma unroll
    for (int j = 0; j < 16; j++) am = fmaxf(am, fabsf(f[j]));
#pragma unroll
    for (int off = 16; off > 0; off >>= 1)
        am = fmaxf(am, __shfl_xor_sync(0xffffffffu, am, off));
    if (lane == 0) warpmax[wid] = am;
    __syncthreads();
    am = warpmax[0];
#pragma unroll
    for (int w = 1; w < 8; w++) am = fmaxf(am, warpmax[w]);

    const float inv = (am > 0.0f) ? 16256.0f / am : 0.0f;
    if (tid == 0) sc[row] = am * (1.0f / 16256.0f);

    __align__(16) char q1[16];
    __align__(16) char q2[32];
#pragma unroll
    for (int j = 0; j < 16; j++) {
        float mf  = rintf(f[j] * inv);            // in [-16256, 16256]
        float a1f = rintf(mf * 0.0078125f);       // /128
        int a1 = (int)a1f;
        int a0 = (int)mf - (a1 << 7);
        q1[j] = (char)a1;
        if (AMODE) { q2[2*j] = (char)a1; q2[2*j+1] = (char)a0; }
        else       { q2[2*j] = (char)a0; q2[2*j+1] = (char)a1; }
    }
    *(uint4*)(c1 + (size_t)row * KDIM + tid * 16) = *(uint4*)q1;
    uint4* d2 = (uint4*)(c2 + (size_t)row * 2 * KDIM + tid * 32);
    d2[0] = *(uint4*)&q2[0];
    d2[1] = *(uint4*)&q2[16];
}

// ---------------------------------------------------------------------------
// IMMA int8 GEMM: C[m,n] = sa[m]*sb[n]*(16384*acc1 + 128*acc2)
// CTA 128(M) x 64(N), 8 warps = 4m x 2n, warp tile 32x32. K=4096, 4-stage.
// ---------------------------------------------------------------------------
#define C1_STR   48
#define C2_STR   80
#define C2_OFF   (192 * C1_STR)                    // 9216
#define IST      (192 * C1_STR + 192 * C2_STR)     // 24576
#define INST     4
#define IGSMEM   (INST * IST)                      // 98304
#define INITER   (KDIM / 32)                       // 128

__global__ void __launch_bounds__(256, 2) gemm_imma(
    const int8_t* __restrict__ A1, const int8_t* __restrict__ A2,
    const int8_t* __restrict__ B1, const int8_t* __restrict__ B2,
    const float* __restrict__ sa, const float* __restrict__ sb,
    float* __restrict__ C, int N)
{
    extern __shared__ __align__(1024) char smem[];
    const uint32_t sbase = smem_u32(smem);

    const int bm = blockIdx.y * 128;
    const int bn = blockIdx.x * 64;
    const int tid = threadIdx.x;
    const int wid = tid >> 5, lane = tid & 31;
    const int wm = wid & 3, wn = wid >> 2;
    const int grp = lane >> 3, lrow = lane & 7;

    const int8_t* ga1 = A1 + (size_t)bm * KDIM;
    const int8_t* ga2 = A2 + (size_t)bm * 2 * KDIM;
    const int8_t* gb1 = B1 + (size_t)bn * KDIM;
    const int8_t* gb2 = B2 + (size_t)bn * 2 * KDIM;

    auto load_stage = [&](int s, int chunk) {
        const uint32_t base = sbase + (uint32_t)s * IST;
        // chain1: 192 rows x 32B = 384 chunks of 16B
#pragma unroll
        for (int j = 0; j < 2; j++) {
            int id = tid + j * 256;
            if (id < 384) {
                int r = id >> 1, c = id & 1;
                const int8_t* src = (r < 128)
                    ? ga1 + (size_t)r * KDIM + chunk * 32 + c * 16
                    : gb1 + (size_t)(r - 128) * KDIM + chunk * 32 + c * 16;
                cp_async16(base + (uint32_t)(r * C1_STR + c * 16), src);
            }
        }
        // chain2: 192 rows x 64B = 768 chunks
#pragma unroll
        for (int j = 0; j < 3; j++) {
            int id = tid + j * 256;
            int r = id >> 2, c = id & 3;
            const int8_t* src = (r < 128)
                ? ga2 + (size_t)r * 2 * KDIM + chunk * 64 + c * 16
                : gb2 + (size_t)(r - 128) * 2 * KDIM + chunk * 64 + c * 16;
            cp_async16(base + (uint32_t)(C2_OFF + r * C2_STR + c * 16), src);
        }
        cp_commit();
    };

    int d1[2][4][4], d2[2][4][4];
#pragma unroll
    for (int mi = 0; mi < 2; mi++)
#pragma unroll
        for (int nj = 0; nj < 4; nj++)
#pragma unroll
            for (int q = 0; q < 4; q++) { d1[mi][nj][q] = 0; d2[mi][nj][q] = 0; }

    const int a_r = lrow + ((grp & 1) << 3);
    const int a_cB = (grp >> 1) << 4;         // 0 or 16 bytes
    const int b_r = lrow + ((grp >> 1) << 3);
    const int b_cB = (grp & 1) << 4;

    load_stage(0, 0);
    load_stage(1, 1);
    load_stage(2, 2);

    for (int i = 0; i < INITER; i++) {
        const int s = i & (INST - 1);
        asm volatile("cp.async.wait_group %0;" :: "n"(INST - 2) : "memory");
        __syncthreads();
        if (i + 3 < INITER) load_stage((i + 3) & (INST - 1), i + 3);
        else cp_commit();

        const uint32_t base = sbase + (uint32_t)s * IST;
        // ---- chain1 (one k32 block) ----
        {
            uint32_t af[2][4];
#pragma unroll
            for (int mi = 0; mi < 2; mi++) {
                uint32_t addr = base + (uint32_t)((wm * 32 + mi * 16 + a_r) * C1_STR + a_cB);
                LDSM_X4(af[mi][0], af[mi][1], af[mi][2], af[mi][3], addr);
            }
#pragma unroll
            for (int np = 0; np < 2; np++) {
                uint32_t b0, b1, b2, b3;
                uint32_t addr = base + (uint32_t)((128 + wn * 32 + np * 16 + b_r) * C1_STR + b_cB);
                LDSM_X4(b0, b1, b2, b3, addr);
#pragma unroll
                for (int mi = 0; mi < 2; mi++) {
                    MMA_S8(d1[mi][2 * np],     af[mi], b0, b1);
                    MMA_S8(d1[mi][2 * np + 1], af[mi], b2, b3);
                }
            }
        }
        // ---- chain2 (two k32 blocks) ----
#pragma unroll
        for (int sub = 0; sub < 2; sub++) {
            uint32_t af[2][4];
#pragma unroll
            for (int mi = 0; mi < 2; mi++) {
                uint32_t addr = base + (uint32_t)(C2_OFF + (wm * 32 + mi * 16 + a_r) * C2_STR
                                                 + sub * 32 + a_cB);
                LDSM_X4(af[mi][0], af[mi][1], af[mi][2], af[mi][3], addr);
            }
#pragma unroll
            for (int np = 0; np < 2; np++) {
                uint32_t b0, b1, b2, b3;
                uint32_t addr = base + (uint32_t)(C2_OFF + (128 + wn * 32 + np * 16 + b_r) * C2_STR
                                                 + sub * 32 + b_cB);
                LDSM_X4(b0, b1, b2, b3, addr);
#pragma unroll
                for (int mi = 0; mi < 2; mi++) {
                    MMA_S8(d2[mi][2 * np],     af[mi], b0, b1);
                    MMA_S8(d2[mi][2 * np + 1], af[mi], b2, b3);
                }
            }
        }
    }

    // epilogue
    const int er = lane >> 2;
    const int ec = (lane & 3) * 2;
#pragma unroll
    for (int mi = 0; mi < 2; mi++) {
#pragma unroll
        for (int nj = 0; nj < 4; nj++) {
            int r0 = bm + wm * 32 + mi * 16 + er;
            int c0 = bn + wn * 32 + nj * 8 + ec;
            float sb0 = sb[c0], sb1 = sb[c0 + 1];
            float sa0 = sa[r0], sa1 = sa[r0 + 8];
            float x0 = sa0 * sb0 * (16384.0f * (float)d1[mi][nj][0] + 128.0f * (float)d2[mi][nj][0]);
            float x1 = sa0 * sb1 * (16384.0f * (float)d1[mi][nj][1] + 128.0f * (float)d2[mi][nj][1]);
            float x2 = sa1 * sb0 * (16384.0f * (float)d1[mi][nj][2] + 128.0f * (float)d2[mi][nj][2]);
            float x3 = sa1 * sb1 * (16384.0f * (float)d1[mi][nj][3] + 128.0f * (float)d2[mi][nj][3]);
            *(float2*)&C[(size_t)r0 * N + c0]       = make_float2(x0, x1);
            *(float2*)&C[(size_t)(r0 + 8) * N + c0] = make_float2(x2, x3);
        }
    }
}

// ---------------------------------------------------------------------------
// RoPE + split for Q/K (R5, proven)
// ---------------------------------------------------------------------------
template <int ISQ>
__global__ void rope_split(const float* __restrict__ src, uint16_t* __restrict__ dst,
                           const float* __restrict__ fc, const float* __restrict__ fs)
{
    const int HEADS = ISQ ? NH : NKV;
    int gid = blockIdx.x * blockDim.x + threadIdx.x;
    int part = gid & 15;
    int row  = gid >> 4;
    int s = row & (SEQ - 1);
    int bh = row >> 11;
    int h = bh % HEADS;
    int b = bh / HEADS;
    const float scale = ISQ ? 0.08838834764831845f : 1.0f;

    const float* in = src + ((size_t)(b * SEQ + s)) * (HEADS * HD) + h * HD + part * 8;
    float vals[8];
    *(float4*)&vals[0] = *(const float4*)&in[0];
    *(float4*)&vals[4] = *(const float4*)&in[4];

    __align__(16) uint16_t o[24];
#pragma unroll
    for (int p = 0; p < 4; p++) {
        int i = part * 4 + p;
        float c  = fc[s * 64 + i];
        float sn = fs[s * 64 + i];
        float xr = vals[2 * p], xi = vals[2 * p + 1];
        float rr = (xr * c - xi * sn) * scale;
        float ri = (xr * sn + xi * c) * scale;
        float f2[2] = {rr, ri};
#pragma unroll
        for (int e = 0; e < 2; e++) {
            uint16_t hb, lb;
            split2(f2[e], hb, lb);
            int j = p * 2 + e;
            if (ISQ) { o[3*j] = hb; o[3*j+1] = lb; o[3*j+2] = hb; }
            else     { o[3*j] = hb; o[3*j+1] = hb; o[3*j+2] = lb; }
        }
    }
    uint4* dp = (uint4*)(dst + (size_t)row * 384 + part * 24);
    dp[0] = *(uint4*)&o[0];
    dp[1] = *(uint4*)&o[8];
    dp[2] = *(uint4*)&o[16];
}

__global__ void split_v_kernel(const float* __restrict__ src, uint16_t* __restrict__ dst)
{
    int gid = blockIdx.x * blockDim.x + threadIdx.x;
    int part = gid & 15;
    int row  = gid >> 4;
    int t = row & (SEQ - 1);
    int bkv = row >> 11;
    int kv = bkv & (NKV - 1);
    int b = bkv >> 3;

    const float* in = src + ((size_t)(b * SEQ + t)) * KVDIM + kv * HD + part * 8;
    float vals[8];
    *(float4*)&vals[0] = *(const float4*)&in[0];
    *(float4*)&vals[4] = *(const float4*)&in[4];

    __align__(16) uint16_t hi8[8], lo8[8];
#pragma unroll
    for (int j = 0; j < 8; j++) {
        uint16_t hb, lb;
        split2(vals[j], hb, lb);
        hi8[j] = hb; lo8[j] = lb;
    }
    uint16_t* out = dst + ((size_t)bkv * (3 * SEQ) + 3 * t) * HD + part * 8;
    *(uint4*)&out[0]        = *(uint4*)&hi8[0];
    *(uint4*)&out[HD]       = *(uint4*)&hi8[0];
    *(uint4*)&out[2 * HD]   = *(uint4*)&lo8[0];
}

// ---------------------------------------------------------------------------
// HMMA causal flash attention (R5, proven ~700us)
// ---------------------------------------------------------------------------
#define SQ_STR   784
#define SK_STR   784
#define SV_STR   272
#define SP_STR   400
#define SQ_OFF   0
#define SK_OFF   50176
#define SV_OFF   100352
#define SP_OFF   152576
#define ATT_SMEM 178176

__global__ void __launch_bounds__(256) attn_mma(
    const uint16_t* __restrict__ Qs, const uint16_t* __restrict__ Ks,
    const uint16_t* __restrict__ Vs, float* __restrict__ Oout)
{
    extern __shared__ __align__(1024) char smem[];
    const uint32_t sQ = smem_u32(smem) + SQ_OFF;
    const uint32_t sK = smem_u32(smem) + SK_OFF;
    const uint32_t sV = smem_u32(smem) + SV_OFF;
    const uint32_t sP = smem_u32(smem) + SP_OFF;
    float* mergeO = (float*)smem;
    float* mergeM = (float*)(smem + 32768);
    float* mergeL = (float*)(smem + 32768 + 256);

    const int qi = (SEQ / 64 - 1) - blockIdx.x;
    const int bh = blockIdx.y;
    const int b = bh >> 5, h = bh & 31, kvh = h >> 2;
    const int q0 = qi * 64;
    const int tid = threadIdx.x;
    const int wid = tid >> 5, lane = tid & 31;
    const int wm = wid & 3, wn = wid >> 2;
    const int grp = lane >> 3, lrow = lane & 7;

    const uint16_t* gq = Qs + ((size_t)(b * NH + h) * SEQ + q0) * 384;
#pragma unroll
    for (int j = 0; j < 12; j++) {
        int id = tid + j * 256;
        int r = id / 48, c = id % 48;
        cp_async16(sQ + (uint32_t)(r * SQ_STR + c * 16), gq + (size_t)r * 384 + c * 8);
    }
    cp_commit();

    float m0 = -1e30f, m1 = -1e30f, l0 = 0.0f, l1 = 0.0f;
    float Oc[16][4];
#pragma unroll
    for (int j = 0; j < 16; j++)
#pragma unroll
        for (int q = 0; q < 4; q++) Oc[j][q] = 0.0f;

    const uint16_t* gk = Ks + ((size_t)(b * NKV + kvh) * SEQ) * 384;
    const uint16_t* gv = Vs + ((size_t)(b * NKV + kvh) * (3 * SEQ)) * HD;

    const int ra = wm * 16 + (lane >> 2);

    for (int kt = 0; kt <= qi; kt++) {
        const int t0 = kt * 64;
        __syncthreads();
#pragma unroll
        for (int j = 0; j < 12; j++) {
            int id = tid + j * 256;
            int r = id / 48, c = id % 48;
            cp_async16(sK + (uint32_t)(r * SK_STR + c * 16),
                       gk + ((size_t)(t0 + r)) * 384 + c * 8);
        }
#pragma unroll
        for (int j = 0; j < 12; j++) {
            int id = tid + j * 256;
            int r = id / 16, c = id % 16;
            cp_async16(sV + (uint32_t)(r * SV_STR + c * 16),
                       gv + ((size_t)(t0 * 3 + r)) * HD + c * 8);
        }
        cp_commit();
        asm volatile("cp.async.wait_group 0;" ::: "memory");
        __syncthreads();

        float Sa[4][4];
#pragma unroll
        for (int nt = 0; nt < 4; nt++)
#pragma unroll
            for (int q = 0; q < 4; q++) Sa[nt][q] = 0.0f;

#pragma unroll
        for (int ks = 0; ks < 24; ks++) {
            uint32_t A[4];
            uint32_t aaddr = sQ + (uint32_t)((wm * 16 + lrow + ((grp & 1) << 3)) * SQ_STR
                                             + (ks * 16 + ((grp >> 1) << 3)) * 2);
            LDSM_X4(A[0], A[1], A[2], A[3], aaddr);
#pragma unroll
            for (int ntp = 0; ntp < 2; ntp++) {
                uint32_t b0, b1, b2, b3;
                uint32_t baddr = sK + (uint32_t)((wn * 32 + ntp * 16 + lrow + ((grp >> 1) << 3)) * SK_STR
                                                 + (ks * 16 + ((grp & 1) << 3)) * 2);
                LDSM_X4(b0, b1, b2, b3, baddr);
                MMA_BF16(Sa[2 * ntp],     A, b0, b1);
                MMA_BF16(Sa[2 * ntp + 1], A, b2, b3);
            }
        }

        if (kt == qi) {
#pragma unroll
            for (int nt = 0; nt < 4; nt++) {
                int tb = wn * 32 + nt * 8 + 2 * (lane & 3);
                if (tb     > ra)     Sa[nt][0] = -1e30f;
                if (tb + 1 > ra)     Sa[nt][1] = -1e30f;
                if (tb     > ra + 8) Sa[nt][2] = -1e30f;
                if (tb + 1 > ra + 8) Sa[nt][3] = -1e30f;
            }
        }

        float hm0 = -1e30f, hm1 = -1e30f;
#pragma unroll
        for (int nt = 0; nt < 4; nt++) {
            hm0 = fmaxf(hm0, fmaxf(Sa[nt][0], Sa[nt][1]));
            hm1 = fmaxf(hm1, fmaxf(Sa[nt][2], Sa[nt][3]));
        }
        hm0 = fmaxf(hm0, __shfl_xor_sync(0xffffffffu, hm0, 1));
        hm0 = fmaxf(hm0, __shfl_xor_sync(0xffffffffu, hm0, 2));
        hm1 = fmaxf(hm1, __shfl_xor_sync(0xffffffffu, hm1, 1));
        hm1 = fmaxf(hm1, __shfl_xor_sync(0xffffffffu, hm1, 2));

        float mn0 = fmaxf(m0, hm0), mn1 = fmaxf(m1, hm1);
        float al0 = __expf(m0 - mn0), al1 = __expf(m1 - mn1);
        m0 = mn0; m1 = mn1;

        float hs0 = 0.0f, hs1 = 0.0f;
#pragma unroll
        for (int nt = 0; nt < 4; nt++) {
            Sa[nt][0] = __expf(Sa[nt][0] - mn0); hs0 += Sa[nt][0];
            Sa[nt][1] = __expf(Sa[nt][1] - mn0); hs0 += Sa[nt][1];
            Sa[nt][2] = __expf(Sa[nt][2] - mn1); hs1 += Sa[nt][2];
            Sa[nt][3] = __expf(Sa[nt][3] - mn1); hs1 += Sa[nt][3];
        }
        hs0 += __shfl_xor_sync(0xffffffffu, hs0, 1);
        hs0 += __shfl_xor_sync(0xffffffffu, hs0, 2);
        hs1 += __shfl_xor_sync(0xffffffffu, hs1, 1);
        hs1 += __shfl_xor_sync(0xffffffffu, hs1, 2);
        l0 = l0 * al0 + hs0;
        l1 = l1 * al1 + hs1;
#pragma unroll
        for (int j = 0; j < 16; j++) {
            Oc[j][0] *= al0; Oc[j][1] *= al0;
            Oc[j][2] *= al1; Oc[j][3] *= al1;
        }

        __syncwarp();
#pragma unroll
        for (int nt = 0; nt < 4; nt++) {
            int tl0 = wn * 32 + nt * 8 + 2 * (lane & 3);
#pragma unroll
            for (int q = 0; q < 4; q++) {
                int row = ra + ((q >> 1) << 3);
                int t = tl0 + (q & 1);
                float p = Sa[nt][q];
                uint16_t hb, lb;
                split2(p, hb, lb);
                uint32_t ad = sP + (uint32_t)(row * SP_STR + t * 6);
                asm volatile("st.shared.u16 [%0], %1;" :: "r"(ad),     "h"(hb));
                asm volatile("st.shared.u16 [%0], %1;" :: "r"(ad + 2), "h"(lb));
                asm volatile("st.shared.u16 [%0], %1;" :: "r"(ad + 4), "h"(hb));
            }
        }
        __syncwarp();

#pragma unroll
        for (int ks2 = 0; ks2 < 6; ks2++) {
            uint32_t A[4];
            uint32_t aaddr = sP + (uint32_t)((wm * 16 + lrow + ((grp & 1) << 3)) * SP_STR
                                             + (wn * 96 + ks2 * 16 + ((grp >> 1) << 3)) * 2);
            LDSM_X4(A[0], A[1], A[2], A[3], aaddr);
#pragma unroll
            for (int ntp = 0; ntp < 8; ntp++) {
                uint32_t b0, b1, b2, b3;
                uint32_t baddr = sV + (uint32_t)((wn * 96 + ks2 * 16 + lrow + ((grp & 1) << 3)) * SV_STR
                                                 + (ntp * 16 + ((grp >> 1) << 3)) * 2);
                LDSM_X4_T(b0, b1, b2, b3, baddr);
                MMA_BF16(Oc[2 * ntp],     A, b0, b1);
                MMA_BF16(Oc[2 * ntp + 1], A, b2, b3);
            }
        }
    }

    __syncthreads();
    if (wn == 1) {
#pragma unroll
        for (int nt = 0; nt < 16; nt++) {
            int col = nt * 8 + 2 * (lane & 3);
            *(float2*)&mergeO[ra * 128 + col]       = make_float2(Oc[nt][0], Oc[nt][1]);
            *(float2*)&mergeO[(ra + 8) * 128 + col] = make_float2(Oc[nt][2], Oc[nt][3]);
        }
        if ((lane & 3) == 0) {
            mergeM[ra] = m0;     mergeM[ra + 8] = m1;
            mergeL[ra] = l0;     mergeL[ra + 8] = l1;
        }
    }
    __syncthreads();
    if (wn == 0) {
        float M1a = mergeM[ra],     L1a = mergeL[ra];
        float M1b = mergeM[ra + 8], L1b = mergeL[ra + 8];
        float Ma = fmaxf(m0, M1a);
        float w0a = __expf(m0 - Ma), w1a = __expf(M1a - Ma);
        float inva = 1.0f / (l0 * w0a + L1a * w1a);
        float Mb = fmaxf(m1, M1b);
        float w0b = __expf(m1 - Mb), w1b = __expf(M1b - Mb);
        float invb = 1.0f / (l1 * w0b + L1b * w1b);

        size_t obase = ((size_t)(b * SEQ + q0)) * DIM + h * HD;
#pragma unroll
        for (int nt = 0; nt < 16; nt++) {
            int col = nt * 8 + 2 * (lane & 3);
            float2 o1a = *(float2*)&mergeO[ra * 128 + col];
            float2 o1b = *(float2*)&mergeO[(ra + 8) * 128 + col];
            float2 oa = make_float2((Oc[nt][0] * w0a + o1a.x * w1a) * inva,
                                    (Oc[nt][1] * w0a + o1a.y * w1a) * inva);
            float2 ob = make_float2((Oc[nt][2] * w0b + o1b.x * w1b) * invb,
                                    (Oc[nt][3] * w0b + o1b.y * w1b) * invb);
            *(float2*)&Oout[obase + (size_t)ra * DIM + col]       = oa;
            *(float2*)&Oout[obase + (size_t)(ra + 8) * DIM + col] = ob;
        }
    }
}

// ---------------------------------------------------------------------------
extern "C" void kernel_launch(void* const* d_in, const int* in_sizes, int n_in,
                              void* d_out, int out_size)
{
    const float* x  = (const float*)d_in[0];
    const float* wq = (const float*)d_in[1];
    const float* wk = (const float*)d_in[2];
    const float* wv = (const float*)d_in[3];
    const float* wo = (const float*)d_in[4];
    const float* fc = (const float*)d_in[5];
    const float* fs = (const float*)d_in[6];
    float* out = (float*)d_out;

    float *qp, *kp, *vp, *ap;
    cudaGetSymbolAddress((void**)&qp, g_q);
    cudaGetSymbolAddress((void**)&kp, g_k);
    cudaGetSymbolAddress((void**)&vp, g_v);
    cudaGetSymbolAddress((void**)&ap, g_attn);

    int8_t *x1, *x2, *at1, *at2, *q1, *q2, *k1, *k2, *v1, *v2, *o1, *o2;
    float *sx, *sat, *swq, *swk, *swv, *swo;
    uint16_t *qs2, *ks2, *vs2;
    cudaGetSymbolAddress((void**)&x1, g_x1);   cudaGetSymbolAddress((void**)&x2, g_x2);
    cudaGetSymbolAddress((void**)&at1, g_at1); cudaGetSymbolAddress((void**)&at2, g_at2);
    cudaGetSymbolAddress((void**)&q1, g_wq1);  cudaGetSymbolAddress((void**)&q2, g_wq2);
    cudaGetSymbolAddress((void**)&k1, g_wk1);  cudaGetSymbolAddress((void**)&k2, g_wk2);
    cudaGetSymbolAddress((void**)&v1, g_wv1);  cudaGetSymbolAddress((void**)&v2, g_wv2);
    cudaGetSymbolAddress((void**)&o1, g_wo1);  cudaGetSymbolAddress((void**)&o2, g_wo2);
    cudaGetSymbolAddress((void**)&sx, g_sx);   cudaGetSymbolAddress((void**)&sat, g_sat);
    cudaGetSymbolAddress((void**)&swq, g_swq); cudaGetSymbolAddress((void**)&swk, g_swk);
    cudaGetSymbolAddress((void**)&swv, g_swv); cudaGetSymbolAddress((void**)&swo, g_swo);
    cudaGetSymbolAddress((void**)&qs2, g_qs2);
    cudaGetSymbolAddress((void**)&ks2, g_ks2);
    cudaGetSymbolAddress((void**)&vs2, g_vs2);

    cudaFuncSetAttribute(gemm_imma, cudaFuncAttributeMaxDynamicSharedMemorySize, IGSMEM);
    cudaFuncSetAttribute(attn_mma, cudaFuncAttributeMaxDynamicSharedMemorySize, ATT_SMEM);

    // Quantize inputs/weights
    quant_row<1><<<MROWS, 256>>>(x,  x1, x2, sx);
    quant_row<0><<<DIM,   256>>>(wq, q1, q2, swq);
    quant_row<0><<<KVDIM, 256>>>(wk, k1, k2, swk);
    quant_row<0><<<KVDIM, 256>>>(wv, v1, v2, swv);
    quant_row<0><<<DIM,   256>>>(wo, o1, o2, swo);

    // QKV projections (IMMA)
    gemm_imma<<<dim3(DIM   / 64, MROWS / 128), 256, IGSMEM>>>(x1, x2, q1, q2, sx, swq, qp, DIM);
    gemm_imma<<<dim3(KVDIM / 64, MROWS / 128), 256, IGSMEM>>>(x1, x2, k1, k2, sx, swk, kp, KVDIM);
    gemm_imma<<<dim3(KVDIM / 64, MROWS / 128), 256, IGSMEM>>>(x1, x2, v1, v2, sx, swv, vp, KVDIM);

    // RoPE + split for attention
    rope_split<1><<<(BATCH * NH  * SEQ * 16) / 256, 256>>>(qp, qs2, fc, fs);
    rope_split<0><<<(BATCH * NKV * SEQ * 16) / 256, 256>>>(kp, ks2, fc, fs);
    split_v_kernel<<<(BATCH * NKV * SEQ * 16) / 256, 256>>>(vp, vs2);

    // HMMA flash attention
    attn_mma<<<dim3(SEQ / 64, BATCH * NH), 256, ATT_SMEM>>>(qs2, ks2, vs2, ap);

    // Output projection (IMMA)
    quant_row<1><<<MROWS, 256>>>(ap, at1, at2, sat);
    gemm_imma<<<dim3(DIM / 64, MROWS / 128), 256, IGSMEM>>>(at1, at2, o1, o2, sat, swo, out, DIM);
}

// round 10
// speedup vs baseline: 1.9379x; 1.9379x over previous
#include <cuda_runtime.h>
#include <cuda_bf16.h>
#include <math.h>
#include <stdint.h>

#define BATCH 2
#define SEQ   2048
#define DIM   4096
#define NH    32
#define NKV   8
#define HD    128
#define MROWS 4096   // BATCH*SEQ
#define KVDIM 1024   // NKV*HD
#define K3    (3 * DIM)   // 12288: split-interleaved K

// ---------------- scratch (zero-init .bss, no runtime allocation) ----------
__device__ float g_q[(size_t)MROWS * DIM];
__device__ float g_k[(size_t)MROWS * KVDIM];
__device__ float g_v[(size_t)MROWS * KVDIM];
__device__ float g_attn[(size_t)MROWS * DIM];

__device__ uint16_t g_xs [(size_t)MROWS * K3];
__device__ uint16_t g_as [(size_t)MROWS * K3];
__device__ uint16_t g_wqs[(size_t)DIM   * K3];
__device__ uint16_t g_wks[(size_t)KVDIM * K3];
__device__ uint16_t g_wvs[(size_t)KVDIM * K3];
__device__ uint16_t g_wos[(size_t)DIM   * K3];

__device__ uint16_t g_qs2[(size_t)BATCH * NH  * SEQ * 384];
__device__ uint16_t g_ks2[(size_t)BATCH * NKV * SEQ * 384];
__device__ uint16_t g_vs2[(size_t)BATCH * NKV * (3*SEQ) * HD];

// ---------------- helpers ---------------------------------------------------
__device__ __forceinline__ uint32_t smem_u32(const void* p) {
    return (uint32_t)__cvta_generic_to_shared(p);
}
__device__ __forceinline__ void cp_async16(uint32_t dst, const void* src) {
    asm volatile("cp.async.cg.shared.global [%0], [%1], 16;" :: "r"(dst), "l"(src) : "memory");
}
__device__ __forceinline__ void cp_commit() {
    asm volatile("cp.async.commit_group;" ::: "memory");
}

#define LDSM_X4(r0, r1, r2, r3, addr) \
    asm volatile("ldmatrix.sync.aligned.m8n8.x4.shared.b16 {%0,%1,%2,%3}, [%4];" \
                 : "=r"(r0), "=r"(r1), "=r"(r2), "=r"(r3) : "r"(addr))

#define LDSM_X4_T(r0, r1, r2, r3, addr) \
    asm volatile("ldmatrix.sync.aligned.m8n8.x4.trans.shared.b16 {%0,%1,%2,%3}, [%4];" \
                 : "=r"(r0), "=r"(r1), "=r"(r2), "=r"(r3) : "r"(addr))

#define MMA_BF16(d, a, b0v, b1v) \
    asm volatile("mma.sync.aligned.m16n8k16.row.col.f32.bf16.bf16.f32 " \
                 "{%0,%1,%2,%3}, {%4,%5,%6,%7}, {%8,%9}, {%0,%1,%2,%3};" \
                 : "+f"((d)[0]), "+f"((d)[1]), "+f"((d)[2]), "+f"((d)[3]) \
                 : "r"((a)[0]), "r"((a)[1]), "r"((a)[2]), "r"((a)[3]), \
                   "r"(b0v), "r"(b1v))

__device__ __forceinline__ void split2(float f, uint16_t& hb, uint16_t& lb) {
    __nv_bfloat16 hi = __float2bfloat16_rn(f);
    __nv_bfloat16 lo = __float2bfloat16_rn(f - __bfloat162float(hi));
    hb = __bfloat16_as_ushort(hi);
    lb = __bfloat16_as_ushort(lo);
}

// ---------------------------------------------------------------------------
// Split fp32 -> bf16 triplets, smem-staged for coalesced output.
// Block handles 2048 consecutive floats -> 6144 uint16 (12KB).
// AMODE=1: (hi,lo,hi); AMODE=0: (hi,hi,lo).
// ---------------------------------------------------------------------------
template <int AMODE>
__global__ void __launch_bounds__(256) split_kernel(
    const float* __restrict__ src, uint16_t* __restrict__ dst)
{
    __shared__ __align__(16) uint16_t stage[6144];
    const size_t base = (size_t)blockIdx.x * 2048;
    const int tid = threadIdx.x;

    float4 v0 = *(const float4*)&src[base + tid * 8];
    float4 v1 = *(const float4*)&src[base + tid * 8 + 4];
    float f[8] = {v0.x, v0.y, v0.z, v0.w, v1.x, v1.y, v1.z, v1.w};
    __align__(16) uint16_t o[24];
#pragma unroll
    for (int j = 0; j < 8; j++) {
        uint16_t hb, lb;
        split2(f[j], hb, lb);
        if (AMODE) { o[3*j] = hb; o[3*j+1] = lb; o[3*j+2] = hb; }
        else       { o[3*j] = hb; o[3*j+1] = hb; o[3*j+2] = lb; }
    }
    uint4* sp = (uint4*)&stage[tid * 24];
    sp[0] = *(uint4*)&o[0];
    sp[1] = *(uint4*)&o[8];
    sp[2] = *(uint4*)&o[16];
    __syncthreads();

    uint4* d4 = (uint4*)(dst + base * 3);
    const uint4* s4 = (const uint4*)stage;
    d4[tid]       = s4[tid];
    d4[tid + 256] = s4[tid + 256];
    d4[tid + 512] = s4[tid + 512];
}

// ---------------------------------------------------------------------------
// HMMA bf16 GEMM (R5 config, proven): 128x128 CTA, warp 32x64, 4-stage,
// 80B rows, 2 CTAs/SM.
// ---------------------------------------------------------------------------
#define BKC         32
#define ROW_BYTES   80
#define STAGE_BYTES (256 * ROW_BYTES)
#define NSTAGE      4
#define GSMEM       (NSTAGE * STAGE_BYTES)
#define NITER       (K3 / BKC)

__global__ void __launch_bounds__(256) gemm_hmma(
    const uint16_t* __restrict__ A, const uint16_t* __restrict__ Bm,
    float* __restrict__ C, int M, int N)
{
    extern __shared__ __align__(1024) char smem[];
    const uint32_t sbase = smem_u32(smem);

    const int bm = blockIdx.y * 128;
    const int bn = blockIdx.x * 128;
    const int tid = threadIdx.x;
    const int wid = tid >> 5;
    const int lane = tid & 31;
    const int wm = wid & 3;
    const int wn = wid >> 2;

    const uint16_t* ga0 = A  + (size_t)bm * K3;
    const uint16_t* gb0 = Bm + (size_t)bn * K3;

    const int lc = tid & 3;
    const int lr = tid >> 2;

    auto load_stage = [&](int s, int chunk) {
        const uint32_t sa = sbase + (uint32_t)s * STAGE_BYTES;
        const size_t koff = (size_t)chunk * BKC + lc * 8;
#pragma unroll
        for (int j = 0; j < 4; j++) {
            int r = lr + j * 64;
            const uint16_t* src = (r < 128)
                ? ga0 + (size_t)r * K3 + koff
                : gb0 + (size_t)(r - 128) * K3 + koff;
            cp_async16(sa + (uint32_t)(r * ROW_BYTES + lc * 16), src);
        }
        cp_commit();
    };

    float d[2][8][4];
#pragma unroll
    for (int mi = 0; mi < 2; mi++)
#pragma unroll
        for (int nj = 0; nj < 8; nj++)
#pragma unroll
            for (int q = 0; q < 4; q++) d[mi][nj][q] = 0.0f;

    const int grp  = lane >> 3;
    const int lrow = lane & 7;
    const int a_r = lrow + ((grp & 1) << 3);
    const int a_c = (grp >> 1) << 3;
    const int b_r = lrow + ((grp >> 1) << 3);
    const int b_c = (grp & 1) << 3;

    load_stage(0, 0);
    load_stage(1, 1);
    load_stage(2, 2);

    for (int i = 0; i < NITER; i++) {
        const int s = i & (NSTAGE - 1);
        asm volatile("cp.async.wait_group %0;" :: "n"(NSTAGE - 2) : "memory");
        __syncthreads();
        if (i + 3 < NITER) load_stage((i + 3) & (NSTAGE - 1), i + 3);
        else cp_commit();

        const uint32_t aB = sbase + (uint32_t)s * STAGE_BYTES;
        const uint32_t bB = aB + 128 * ROW_BYTES;
#pragma unroll
        for (int step = 0; step < 2; step++) {
            uint32_t af[2][4];
#pragma unroll
            for (int mi = 0; mi < 2; mi++) {
                uint32_t addr = aB + (uint32_t)((wm * 32 + mi * 16 + a_r) * ROW_BYTES
                                                + (step * 16 + a_c) * 2);
                LDSM_X4(af[mi][0], af[mi][1], af[mi][2], af[mi][3], addr);
            }
#pragma unroll
            for (int njp = 0; njp < 4; njp++) {
                uint32_t b0, b1, b2, b3;
                uint32_t addr = bB + (uint32_t)((wn * 64 + njp * 16 + b_r) * ROW_BYTES
                                                + (step * 16 + b_c) * 2);
                LDSM_X4(b0, b1, b2, b3, addr);
#pragma unroll
                for (int mi = 0; mi < 2; mi++) {
                    MMA_BF16(d[mi][2 * njp],     af[mi], b0, b1);
                    MMA_BF16(d[mi][2 * njp + 1], af[mi], b2, b3);
                }
            }
        }
    }

    const int er = lane >> 2;
    const int ec = (lane & 3) * 2;
#pragma unroll
    for (int mi = 0; mi < 2; mi++) {
#pragma unroll
        for (int nj = 0; nj < 8; nj++) {
            int r0 = bm + wm * 32 + mi * 16 + er;
            int c0 = bn + wn * 64 + nj * 8 + ec;
            *(float2*)&C[(size_t)r0 * N + c0]       = make_float2(d[mi][nj][0], d[mi][nj][1]);
            *(float2*)&C[(size_t)(r0 + 8) * N + c0] = make_float2(d[mi][nj][2], d[mi][nj][3]);
        }
    }
}

// ---------------------------------------------------------------------------
// RoPE + split for Q/K (R5, proven)
// ---------------------------------------------------------------------------
template <int ISQ>
__global__ void rope_split(const float* __restrict__ src, uint16_t* __restrict__ dst,
                           const float* __restrict__ fc, const float* __restrict__ fs)
{
    const int HEADS = ISQ ? NH : NKV;
    int gid = blockIdx.x * blockDim.x + threadIdx.x;
    int part = gid & 15;
    int row  = gid >> 4;
    int s = row & (SEQ - 1);
    int bh = row >> 11;
    int h = bh % HEADS;
    int b = bh / HEADS;
    const float scale = ISQ ? 0.08838834764831845f : 1.0f;

    const float* in = src + ((size_t)(b * SEQ + s)) * (HEADS * HD) + h * HD + part * 8;
    float vals[8];
    *(float4*)&vals[0] = *(const float4*)&in[0];
    *(float4*)&vals[4] = *(const float4*)&in[4];

    __align__(16) uint16_t o[24];
#pragma unroll
    for (int p = 0; p < 4; p++) {
        int i = part * 4 + p;
        float c  = fc[s * 64 + i];
        float sn = fs[s * 64 + i];
        float xr = vals[2 * p], xi = vals[2 * p + 1];
        float rr = (xr * c - xi * sn) * scale;
        float ri = (xr * sn + xi * c) * scale;
        float f2[2] = {rr, ri};
#pragma unroll
        for (int e = 0; e < 2; e++) {
            uint16_t hb, lb;
            split2(f2[e], hb, lb);
            int j = p * 2 + e;
            if (ISQ) { o[3*j] = hb; o[3*j+1] = lb; o[3*j+2] = hb; }
            else     { o[3*j] = hb; o[3*j+1] = hb; o[3*j+2] = lb; }
        }
    }
    uint4* dp = (uint4*)(dst + (size_t)row * 384 + part * 24);
    dp[0] = *(uint4*)&o[0];
    dp[1] = *(uint4*)&o[8];
    dp[2] = *(uint4*)&o[16];
}

__global__ void split_v_kernel(const float* __restrict__ src, uint16_t* __restrict__ dst)
{
    int gid = blockIdx.x * blockDim.x + threadIdx.x;
    int part = gid & 15;
    int row  = gid >> 4;
    int t = row & (SEQ - 1);
    int bkv = row >> 11;
    int kv = bkv & (NKV - 1);
    int b = bkv >> 3;

    const float* in = src + ((size_t)(b * SEQ + t)) * KVDIM + kv * HD + part * 8;
    float vals[8];
    *(float4*)&vals[0] = *(const float4*)&in[0];
    *(float4*)&vals[4] = *(const float4*)&in[4];

    __align__(16) uint16_t hi8[8], lo8[8];
#pragma unroll
    for (int j = 0; j < 8; j++) {
        uint16_t hb, lb;
        split2(vals[j], hb, lb);
        hi8[j] = hb; lo8[j] = lb;
    }
    uint16_t* out = dst + ((size_t)bkv * (3 * SEQ) + 3 * t) * HD + part * 8;
    *(uint4*)&out[0]        = *(uint4*)&hi8[0];
    *(uint4*)&out[HD]       = *(uint4*)&hi8[0];
    *(uint4*)&out[2 * HD]   = *(uint4*)&lo8[0];
}

// ---------------------------------------------------------------------------
// HMMA causal flash attention. R5 core + K-prefetch: after S-phase consumes
// sK, K(kt+1) loads overlap softmax + PV.
// ---------------------------------------------------------------------------
#define SQ_STR   784
#define SK_STR   784
#define SV_STR   272
#define SP_STR   400
#define SQ_OFF   0
#define SK_OFF   50176
#define SV_OFF   100352
#define SP_OFF   152576
#define ATT_SMEM 178176

__global__ void __launch_bounds__(256) attn_mma(
    const uint16_t* __restrict__ Qs, const uint16_t* __restrict__ Ks,
    const uint16_t* __restrict__ Vs, float* __restrict__ Oout)
{
    extern __shared__ __align__(1024) char smem[];
    const uint32_t sQ = smem_u32(smem) + SQ_OFF;
    const uint32_t sK = smem_u32(smem) + SK_OFF;
    const uint32_t sV = smem_u32(smem) + SV_OFF;
    const uint32_t sP = smem_u32(smem) + SP_OFF;
    float* mergeO = (float*)smem;
    float* mergeM = (float*)(smem + 32768);
    float* mergeL = (float*)(smem + 32768 + 256);

    const int qi = (SEQ / 64 - 1) - blockIdx.x;
    const int bh = blockIdx.y;
    const int b = bh >> 5, h = bh & 31, kvh = h >> 2;
    const int q0 = qi * 64;
    const int tid = threadIdx.x;
    const int wid = tid >> 5, lane = tid & 31;
    const int wm = wid & 3, wn = wid >> 2;
    const int grp = lane >> 3, lrow = lane & 7;

    const uint16_t* gk = Ks + ((size_t)(b * NKV + kvh) * SEQ) * 384;
    const uint16_t* gv = Vs + ((size_t)(b * NKV + kvh) * (3 * SEQ)) * HD;

    auto load_k = [&](int t0) {
#pragma unroll
        for (int j = 0; j < 12; j++) {
            int id = tid + j * 256;
            int r = id / 48, c = id % 48;
            cp_async16(sK + (uint32_t)(r * SK_STR + c * 16),
                       gk + ((size_t)(t0 + r)) * 384 + c * 8);
        }
        cp_commit();
    };
    auto load_v = [&](int t0) {
#pragma unroll
        for (int j = 0; j < 12; j++) {
            int id = tid + j * 256;
            int r = id / 16, c = id % 16;
            cp_async16(sV + (uint32_t)(r * SV_STR + c * 16),
                       gv + ((size_t)(t0 * 3 + r)) * HD + c * 8);
        }
        cp_commit();
    };

    // Q tile + first K/V
    const uint16_t* gq = Qs + ((size_t)(b * NH + h) * SEQ + q0) * 384;
#pragma unroll
    for (int j = 0; j < 12; j++) {
        int id = tid + j * 256;
        int r = id / 48, c = id % 48;
        cp_async16(sQ + (uint32_t)(r * SQ_STR + c * 16), gq + (size_t)r * 384 + c * 8);
    }
    cp_commit();
    load_k(0);
    load_v(0);

    float m0 = -1e30f, m1 = -1e30f, l0 = 0.0f, l1 = 0.0f;
    float Oc[16][4];
#pragma unroll
    for (int j = 0; j < 16; j++)
#pragma unroll
        for (int q = 0; q < 4; q++) Oc[j][q] = 0.0f;

    const int ra = wm * 16 + (lane >> 2);

    for (int kt = 0; kt <= qi; kt++) {
        asm volatile("cp.async.wait_group 0;" ::: "memory");
        __syncthreads();

        // ---- S = Q' K'^T ----
        float Sa[4][4];
#pragma unroll
        for (int nt = 0; nt < 4; nt++)
#pragma unroll
            for (int q = 0; q < 4; q++) Sa[nt][q] = 0.0f;

#pragma unroll
        for (int ks = 0; ks < 24; ks++) {
            uint32_t A[4];
            uint32_t aaddr = sQ + (uint32_t)((wm * 16 + lrow + ((grp & 1) << 3)) * SQ_STR
                                             + (ks * 16 + ((grp >> 1) << 3)) * 2);
            LDSM_X4(A[0], A[1], A[2], A[3], aaddr);
#pragma unroll
            for (int ntp = 0; ntp < 2; ntp++) {
                uint32_t b0, b1, b2, b3;
                uint32_t baddr = sK + (uint32_t)((wn * 32 + ntp * 16 + lrow + ((grp >> 1) << 3)) * SK_STR
                                                 + (ks * 16 + ((grp & 1) << 3)) * 2);
                LDSM_X4(b0, b1, b2, b3, baddr);
                MMA_BF16(Sa[2 * ntp],     A, b0, b1);
                MMA_BF16(Sa[2 * ntp + 1], A, b2, b3);
            }
        }

        // sK now dead for this tile -> prefetch next K under softmax+PV
        __syncthreads();
        if (kt < qi) load_k((kt + 1) * 64);

        if (kt == qi) {
#pragma unroll
            for (int nt = 0; nt < 4; nt++) {
                int tb = wn * 32 + nt * 8 + 2 * (lane & 3);
                if (tb     > ra)     Sa[nt][0] = -1e30f;
                if (tb + 1 > ra)     Sa[nt][1] = -1e30f;
                if (tb     > ra + 8) Sa[nt][2] = -1e30f;
                if (tb + 1 > ra + 8) Sa[nt][3] = -1e30f;
            }
        }

        float hm0 = -1e30f, hm1 = -1e30f;
#pragma unroll
        for (int nt = 0; nt < 4; nt++) {
            hm0 = fmaxf(hm0, fmaxf(Sa[nt][0], Sa[nt][1]));
            hm1 = fmaxf(hm1, fmaxf(Sa[nt][2], Sa[nt][3]));
        }
        hm0 = fmaxf(hm0, __shfl_xor_sync(0xffffffffu, hm0, 1));
        hm0 = fmaxf(hm0, __shfl_xor_sync(0xffffffffu, hm0, 2));
        hm1 = fmaxf(hm1, __shfl_xor_sync(0xffffffffu, hm1, 1));
        hm1 = fmaxf(hm1, __shfl_xor_sync(0xffffffffu, hm1, 2));

        float mn0 = fmaxf(m0, hm0), mn1 = fmaxf(m1, hm1);
        float al0 = __expf(m0 - mn0), al1 = __expf(m1 - mn1);
        m0 = mn0; m1 = mn1;

        float hs0 = 0.0f, hs1 = 0.0f;
#pragma unroll
        for (int nt = 0; nt < 4; nt++) {
            Sa[nt][0] = __expf(Sa[nt][0] - mn0); hs0 += Sa[nt][0];
            Sa[nt][1] = __expf(Sa[nt][1] - mn0); hs0 += Sa[nt][1];
            Sa[nt][2] = __expf(Sa[nt][2] - mn1); hs1 += Sa[nt][2];
            Sa[nt][3] = __expf(Sa[nt][3] - mn1); hs1 += Sa[nt][3];
        }
        hs0 += __shfl_xor_sync(0xffffffffu, hs0, 1);
        hs0 += __shfl_xor_sync(0xffffffffu, hs0, 2);
        hs1 += __shfl_xor_sync(0xffffffffu, hs1, 1);
        hs1 += __shfl_xor_sync(0xffffffffu, hs1, 2);
        l0 = l0 * al0 + hs0;
        l1 = l1 * al1 + hs1;
#pragma unroll
        for (int j = 0; j < 16; j++) {
            Oc[j][0] *= al0; Oc[j][1] *= al0;
            Oc[j][2] *= al1; Oc[j][3] *= al1;
        }

        __syncwarp();
#pragma unroll
        for (int nt = 0; nt < 4; nt++) {
            int tl0 = wn * 32 + nt * 8 + 2 * (lane & 3);
#pragma unroll
            for (int q = 0; q < 4; q++) {
                int row = ra + ((q >> 1) << 3);
                int t = tl0 + (q & 1);
                float p = Sa[nt][q];
                uint16_t hb, lb;
                split2(p, hb, lb);
                uint32_t ad = sP + (uint32_t)(row * SP_STR + t * 6);
                asm volatile("st.shared.u16 [%0], %1;" :: "r"(ad),     "h"(hb));
                asm volatile("st.shared.u16 [%0], %1;" :: "r"(ad + 2), "h"(lb));
                asm volatile("st.shared.u16 [%0], %1;" :: "r"(ad + 4), "h"(hb));
            }
        }
        __syncwarp();

        // ---- O += P' V' ----
#pragma unroll
        for (int ks2 = 0; ks2 < 6; ks2++) {
            uint32_t A[4];
            uint32_t aaddr = sP + (uint32_t)((wm * 16 + lrow + ((grp & 1) << 3)) * SP_STR
                                             + (wn * 96 + ks2 * 16 + ((grp >> 1) << 3)) * 2);
            LDSM_X4(A[0], A[1], A[2], A[3], aaddr);
#pragma unroll
            for (int ntp = 0; ntp < 8; ntp++) {
                uint32_t b0, b1, b2, b3;
                uint32_t baddr = sV + (uint32_t)((wn * 96 + ks2 * 16 + lrow + ((grp & 1) << 3)) * SV_STR
                                                 + (ntp * 16 + ((grp >> 1) << 3)) * 2);
                LDSM_X4_T(b0, b1, b2, b3, baddr);
                MMA_BF16(Oc[2 * ntp],     A, b0, b1);
                MMA_BF16(Oc[2 * ntp + 1], A, b2, b3);
            }
        }

        // sV dead -> issue next V load
        __syncthreads();
        if (kt < qi) load_v((kt + 1) * 64);
    }

    // ---- merge t-halves ----
    __syncthreads();
    if (wn == 1) {
#pragma unroll
        for (int nt = 0; nt < 16; nt++) {
            int col = nt * 8 + 2 * (lane & 3);
            *(float2*)&mergeO[ra * 128 + col]       = make_float2(Oc[nt][0], Oc[nt][1]);
            *(float2*)&mergeO[(ra + 8) * 128 + col] = make_float2(Oc[nt][2], Oc[nt][3]);
        }
        if ((lane & 3) == 0) {
            mergeM[ra] = m0;     mergeM[ra + 8] = m1;
            mergeL[ra] = l0;     mergeL[ra + 8] = l1;
        }
    }
    __syncthreads();
    if (wn == 0) {
        float M1a = mergeM[ra],     L1a = mergeL[ra];
        float M1b = mergeM[ra + 8], L1b = mergeL[ra + 8];
        float Ma = fmaxf(m0, M1a);
        float w0a = __expf(m0 - Ma), w1a = __expf(M1a - Ma);
        float inva = 1.0f / (l0 * w0a + L1a * w1a);
        float Mb = fmaxf(m1, M1b);
        float w0b = __expf(m1 - Mb), w1b = __expf(M1b - Mb);
        float invb = 1.0f / (l1 * w0b + L1b * w1b);

        size_t obase = ((size_t)(b * SEQ + q0)) * DIM + h * HD;
#pragma unroll
        for (int nt = 0; nt < 16; nt++) {
            int col = nt * 8 + 2 * (lane & 3);
            float2 o1a = *(float2*)&mergeO[ra * 128 + col];
            float2 o1b = *(float2*)&mergeO[(ra + 8) * 128 + col];
            float2 oa = make_float2((Oc[nt][0] * w0a + o1a.x * w1a) * inva,
                                    (Oc[nt][1] * w0a + o1a.y * w1a) * inva);
            float2 ob = make_float2((Oc[nt][2] * w0b + o1b.x * w1b) * invb,
                                    (Oc[nt][3] * w0b + o1b.y * w1b) * invb);
            *(float2*)&Oout[obase + (size_t)ra * DIM + col]       = oa;
            *(float2*)&Oout[obase + (size_t)(ra + 8) * DIM + col] = ob;
        }
    }
}

// ---------------------------------------------------------------------------
extern "C" void kernel_launch(void* const* d_in, const int* in_sizes, int n_in,
                              void* d_out, int out_size)
{
    const float* x  = (const float*)d_in[0];
    const float* wq = (const float*)d_in[1];
    const float* wk = (const float*)d_in[2];
    const float* wv = (const float*)d_in[3];
    const float* wo = (const float*)d_in[4];
    const float* fc = (const float*)d_in[5];
    const float* fs = (const float*)d_in[6];
    float* out = (float*)d_out;

    float *qp, *kp, *vp, *ap;
    uint16_t *xs, *as, *wqs, *wks, *wvs, *wos, *qs2, *ks2, *vs2;
    cudaGetSymbolAddress((void**)&qp, g_q);
    cudaGetSymbolAddress((void**)&kp, g_k);
    cudaGetSymbolAddress((void**)&vp, g_v);
    cudaGetSymbolAddress((void**)&ap, g_attn);
    cudaGetSymbolAddress((void**)&xs, g_xs);
    cudaGetSymbolAddress((void**)&as, g_as);
    cudaGetSymbolAddress((void**)&wqs, g_wqs);
    cudaGetSymbolAddress((void**)&wks, g_wks);
    cudaGetSymbolAddress((void**)&wvs, g_wvs);
    cudaGetSymbolAddress((void**)&wos, g_wos);
    cudaGetSymbolAddress((void**)&qs2, g_qs2);
    cudaGetSymbolAddress((void**)&ks2, g_ks2);
    cudaGetSymbolAddress((void**)&vs2, g_vs2);

    cudaFuncSetAttribute(gemm_hmma, cudaFuncAttributeMaxDynamicSharedMemorySize, GSMEM);
    cudaFuncSetAttribute(attn_mma, cudaFuncAttributeMaxDynamicSharedMemorySize, ATT_SMEM);

    // Split inputs (smem-staged, coalesced)
    split_kernel<1><<<(MROWS * DIM) / 2048, 256>>>(x,  xs);
    split_kernel<0><<<(MROWS * DIM) / 2048, 256>>>(wq, wqs);
    split_kernel<0><<<(KVDIM * DIM) / 2048, 256>>>(wk, wks);
    split_kernel<0><<<(KVDIM * DIM) / 2048, 256>>>(wv, wvs);
    split_kernel<0><<<(MROWS * DIM) / 2048, 256>>>(wo, wos);

    // QKV projections (HMMA)
    gemm_hmma<<<dim3(DIM   / 128, MROWS / 128), 256, GSMEM>>>(xs, wqs, qp, MROWS, DIM);
    gemm_hmma<<<dim3(KVDIM / 128, MROWS / 128), 256, GSMEM>>>(xs, wks, kp, MROWS, KVDIM);
    gemm_hmma<<<dim3(KVDIM / 128, MROWS / 128), 256, GSMEM>>>(xs, wvs, vp, MROWS, KVDIM);

    // RoPE + split for attention operands
    rope_split<1><<<(BATCH * NH  * SEQ * 16) / 256, 256>>>(qp, qs2, fc, fs);
    rope_split<0><<<(BATCH * NKV * SEQ * 16) / 256, 256>>>(kp, ks2, fc, fs);
    split_v_kernel<<<(BATCH * NKV * SEQ * 16) / 256, 256>>>(vp, vs2);

    // HMMA flash attention (K-prefetch pipelined)
    attn_mma<<<dim3(SEQ / 64, BATCH * NH), 256, ATT_SMEM>>>(qs2, ks2, vs2, ap);

    // Output projection
    split_kernel<1><<<(MROWS * DIM) / 2048, 256>>>(ap, as);
    gemm_hmma<<<dim3(DIM / 128, MROWS / 128), 256, GSMEM>>>(as, wos, out, MROWS, DIM);
}